// round 3
// baseline (speedup 1.0000x reference)
#include <cuda_runtime.h>

#define T_STEPS 1024
#define BATCH   256
#define HID     512
#define NBLK    128
#define THREADS 512
#define KS      4                 // k-split factor
#define KRANGE  (HID / KS)        // 128 k per split
#define UPB     4                 // hidden units per block
#define GROWS   16                // gate rows per block (4 units x 4 gates)

// Persistent device state (allocation-free scratch)
__device__ float g_h[2][HID * BATCH];   // h[k][b]
__device__ float g_zxT[64 * BATCH];     // zx transposed [col][b]
__device__ float g_zeT[16 * BATCH];     // ze logits transposed [col][b]
__device__ unsigned int g_cnt;          // zero-initialized
__device__ unsigned int g_gen;          // zero-initialized

// ---------- helpers ----------
__device__ __forceinline__ void ffma2(unsigned long long& d,
                                      unsigned long long a,
                                      unsigned long long b) {
    asm("fma.rn.f32x2 %0, %1, %2, %0;" : "+l"(d) : "l"(a), "l"(b));
}
__device__ __forceinline__ unsigned long long addf32x2(unsigned long long a,
                                                       unsigned long long b) {
    unsigned long long r;
    asm("add.rn.f32x2 %0, %1, %2;" : "=l"(r) : "l"(a), "l"(b));
    return r;
}
__device__ __forceinline__ unsigned long long bcast2(float v) {
    unsigned long long r;
    asm("mov.b64 %0, {%1, %1};" : "=l"(r) : "f"(v));
    return r;
}
__device__ __forceinline__ unsigned long long pack2(float lo, float hi) {
    unsigned long long r;
    asm("mov.b64 %0, {%1, %2};" : "=l"(r) : "f"(lo), "f"(hi));
    return r;
}
__device__ __forceinline__ float lo2(unsigned long long v) {
    return __uint_as_float((unsigned int)v);
}
__device__ __forceinline__ float hi2(unsigned long long v) {
    return __uint_as_float((unsigned int)(v >> 32));
}
__device__ __forceinline__ float sigf(float v) {
    return __fdividef(1.0f, 1.0f + __expf(-v));
}
__device__ __forceinline__ float tanh_fast(float v) {
    return __fdividef(2.0f, 1.0f + __expf(-2.0f * v)) - 1.0f;
}

// Generation-counter grid barrier (all NBLK blocks participate)
__device__ __forceinline__ void gsync() {
    __syncthreads();
    if (threadIdx.x == 0) {
        volatile unsigned int* genp = &g_gen;
        unsigned int g = *genp;
        __threadfence();
        if (atomicAdd(&g_cnt, 1u) == NBLK - 1u) {
            atomicExch(&g_cnt, 0u);
            __threadfence();
            *genp = g + 1u;
        } else {
            while (*genp == g) { }
        }
    }
    __syncthreads();
}

// ---------- main persistent kernel ----------
extern "C" __global__ void __launch_bounds__(THREADS, 1)
lstm_persist(const float* __restrict__ x, const float* __restrict__ a,
             const float* __restrict__ y,
             const float* __restrict__ W_ih, const float* __restrict__ W_hh,
             const float* __restrict__ b_ih, const float* __restrict__ b_hh,
             const float* __restrict__ W_eta, const float* __restrict__ b_eta,
             const float* __restrict__ W_xi,  const float* __restrict__ b_xi,
             const float* __restrict__ W_zeta, const float* __restrict__ b_zeta,
             float* __restrict__ out) {
    // Skewed weight tile: physical float index = k*16 + (k>>7)*4 + l.
    // The +4-float skew per k-split group puts the 4 concurrent hk lane-groups
    // in disjoint bank quartets -> conflict-free LDS.128 broadcasts.
    __shared__ __align__(16) float sW[HID * GROWS + KS * 4];
    __shared__ float sWx[GROWS], sWa[GROWS], sWy[GROWS], sB[GROWS];

    const int tid = threadIdx.x;
    const int b2  = tid >> 2;        // batch pair index (0..127): batches 2*b2, 2*b2+1
    const int hk  = tid & 3;         // k-split lane (adjacent lanes in warp)
    const int bid = blockIdx.x;
    const int j0  = bid * UPB;       // first hidden unit owned by this block

    // Load this block's W_hh slice into smem, transposed+skewed.
    // local row l = u*4 + g  ->  global gate row = g*HID + j0 + u
    for (int idx = tid; idx < HID * GROWS; idx += THREADS) {
        int k = idx >> 4, l = idx & 15;
        int u = l >> 2,  g = l & 3;
        int row = g * HID + j0 + u;
        sW[k * 16 + (k >> 7) * 4 + l] = W_hh[row * HID + k];
    }
    if (tid < GROWS) {
        int u = tid >> 2, g = tid & 3;
        int row = g * HID + j0 + u;
        sWx[tid] = W_ih[row * 3 + 0];
        sWa[tid] = W_ih[row * 3 + 1];
        sWy[tid] = W_ih[row * 3 + 2];
        sB[tid]  = b_ih[row] + b_hh[row];
    }

    // Init: zero h (each thread owns unit j0+hk, batches 2*b2..2*b2+1).
    __stcg(reinterpret_cast<float2*>(&g_h[0][(j0 + hk) * BATCH + 2 * b2]),
           make_float2(0.0f, 0.0f));
    float c0 = 0.0f, c1 = 0.0f;      // cell state lives in registers
    gsync();

    const float* sWk = sW + hk * (KRANGE * 16 + 4);  // this split's skewed base

    int cur = 0;
    for (int s = 0; s < T_STEPS; s++) {
        const int t = T_STEPS - 1 - s;   // reversed sequence

        // 16 accumulators: acc[0..7] = batch0 gate pairs, acc[8..15] = batch1.
        unsigned long long acc[16];
        if (hk == 0) {
            const float2 xv = __ldg(reinterpret_cast<const float2*>(&x[t * BATCH + 2 * b2]));
            const float2 av = __ldg(reinterpret_cast<const float2*>(&a[t * BATCH + 2 * b2]));
            const float2 yv = __ldg(reinterpret_cast<const float2*>(&y[t * BATCH + 2 * b2]));
            #pragma unroll
            for (int p = 0; p < 8; p++) {
                float wx0 = sWx[2*p], wx1 = sWx[2*p+1];
                float wa0 = sWa[2*p], wa1 = sWa[2*p+1];
                float wy0 = sWy[2*p], wy1 = sWy[2*p+1];
                float bb0 = sB[2*p],  bb1 = sB[2*p+1];
                acc[p] = pack2(
                    fmaf(wx0, xv.x, fmaf(wa0, av.x, fmaf(wy0, yv.x, bb0))),
                    fmaf(wx1, xv.x, fmaf(wa1, av.x, fmaf(wy1, yv.x, bb1))));
                acc[8 + p] = pack2(
                    fmaf(wx0, xv.y, fmaf(wa0, av.y, fmaf(wy0, yv.y, bb0))),
                    fmaf(wx1, xv.y, fmaf(wa1, av.y, fmaf(wy1, yv.y, bb1))));
            }
        } else {
            #pragma unroll
            for (int p = 0; p < 16; p++) acc[p] = 0ull;
        }

        // h slice for this split: k in [hk*KRANGE, hk*KRANGE+KRANGE)
        const float* hbase = g_h[cur] + hk * KRANGE * BATCH + 2 * b2;

        float2 hbuf[4];
        #pragma unroll
        for (int i = 0; i < 4; i++)
            hbuf[i] = __ldcg(reinterpret_cast<const float2*>(hbase + i * BATCH));

        for (int ib = 0; ib < KRANGE; ib += 4) {
            #pragma unroll
            for (int j = 0; j < 4; j++) {
                float2 hv = hbuf[j];
                int ni = ib + 4 + j;
                hbuf[j] = (ni < KRANGE)
                        ? __ldcg(reinterpret_cast<const float2*>(hbase + ni * BATCH))
                        : make_float2(0.0f, 0.0f);

                const ulonglong2* wr =
                    reinterpret_cast<const ulonglong2*>(sWk + (ib + j) * 16);
                ulonglong2 w0 = wr[0], w1 = wr[1], w2 = wr[2], w3 = wr[3];
                unsigned long long ha = bcast2(hv.x);
                unsigned long long hb = bcast2(hv.y);
                ffma2(acc[0], ha, w0.x); ffma2(acc[1], ha, w0.y);
                ffma2(acc[2], ha, w1.x); ffma2(acc[3], ha, w1.y);
                ffma2(acc[4], ha, w2.x); ffma2(acc[5], ha, w2.y);
                ffma2(acc[6], ha, w3.x); ffma2(acc[7], ha, w3.y);
                ffma2(acc[8],  hb, w0.x); ffma2(acc[9],  hb, w0.y);
                ffma2(acc[10], hb, w1.x); ffma2(acc[11], hb, w1.y);
                ffma2(acc[12], hb, w2.x); ffma2(acc[13], hb, w2.y);
                ffma2(acc[14], hb, w3.x); ffma2(acc[15], hb, w3.y);
            }
        }

        // Cross-split reduction: the 4 hk lanes are adjacent -> butterfly shuffle.
        #pragma unroll
        for (int p = 0; p < 16; p++) {
            acc[p] = addf32x2(acc[p], __shfl_xor_sync(0xffffffffu, acc[p], 1));
            acc[p] = addf32x2(acc[p], __shfl_xor_sync(0xffffffffu, acc[p], 2));
        }

        // Lane hk handles hidden unit j0+hk for both batches.
        unsigned long long pa0, pa1, pb0, pb1;
        if (hk == 0)      { pa0 = acc[0]; pa1 = acc[1]; pb0 = acc[8];  pb1 = acc[9];  }
        else if (hk == 1) { pa0 = acc[2]; pa1 = acc[3]; pb0 = acc[10]; pb1 = acc[11]; }
        else if (hk == 2) { pa0 = acc[4]; pa1 = acc[5]; pb0 = acc[12]; pb1 = acc[13]; }
        else              { pa0 = acc[6]; pa1 = acc[7]; pb0 = acc[14]; pb1 = acc[15]; }

        // pair0 = (i, f), pair1 = (g, o)
        float cn0 = sigf(hi2(pa0)) * c0 + sigf(lo2(pa0)) * tanh_fast(lo2(pa1));
        float h0  = sigf(hi2(pa1)) * tanh_fast(cn0);
        c0 = cn0;
        float cn1 = sigf(hi2(pb0)) * c1 + sigf(lo2(pb0)) * tanh_fast(lo2(pb1));
        float h1  = sigf(hi2(pb1)) * tanh_fast(cn1);
        c1 = cn1;

        __stcg(reinterpret_cast<float2*>(&g_h[cur ^ 1][(j0 + hk) * BATCH + 2 * b2]),
               make_float2(h0, h1));
        gsync();
        cur ^= 1;
    }

    const float* hf = g_h[cur];   // final hidden state [k][b]

    // ---- Phase A: zx columns (blocks 0..63), ze logits (blocks 64..79) ----
    if (tid < BATCH) {
        const int b = tid;
        if (bid < 64) {
            const int m = bid;
            float acc = b_xi[m];
            const float* wm = W_xi + m * HID;
            #pragma unroll 8
            for (int k = 0; k < HID; k++)
                acc = fmaf(__ldcg(hf + k * BATCH + b), __ldg(&wm[k]), acc);
            out[b * 64 + m] = acc;                  // zx at offset 0: [B][64]
            __stcg(&g_zxT[m * BATCH + b], acc);
        } else if (bid < 80) {
            const int e = bid - 64;
            float acc = b_eta[e];
            const float* we = W_eta + e * HID;
            #pragma unroll 8
            for (int k = 0; k < HID; k++)
                acc = fmaf(__ldcg(hf + k * BATCH + b), __ldg(&we[k]), acc);
            __stcg(&g_zeT[e * BATCH + b], acc);
        }
    }
    gsync();

    // ---- Phase B: zy columns (blocks 0..63), ze softmax (block 64) ----
    if (tid < BATCH) {
        const int b = tid;
        if (bid < 64) {
            const int m = bid;
            float acc = b_zeta[m];
            const float* wz = W_zeta + m * (HID + 64);
            #pragma unroll 8
            for (int k = 0; k < HID; k++)
                acc = fmaf(__ldcg(hf + k * BATCH + b), __ldg(&wz[k]), acc);
            #pragma unroll
            for (int j = 0; j < 64; j++)
                acc = fmaf(__ldcg(&g_zxT[j * BATCH + b]), __ldg(&wz[HID + j]), acc);
            out[16384 + b * 64 + m] = acc;          // zy at offset 16384: [B][64]
        } else if (bid == 64) {
            float l[16];
            float mx = -1e30f;
            #pragma unroll
            for (int e = 0; e < 16; e++) {
                l[e] = __ldcg(&g_zeT[e * BATCH + b]);
                mx = fmaxf(mx, l[e]);
            }
            float ssum = 0.0f;
            #pragma unroll
            for (int e = 0; e < 16; e++) { l[e] = __expf(l[e] - mx); ssum += l[e]; }
            float inv = __fdividef(1.0f, ssum);
            #pragma unroll
            for (int e = 0; e < 16; e++)
                out[32768 + b * 16 + e] = l[e] * inv;   // ze at offset 32768: [B][16]
        }
    }
}

extern "C" void kernel_launch(void* const* d_in, const int* in_sizes, int n_in,
                              void* d_out, int out_size) {
    const float* x      = (const float*)d_in[0];
    const float* a      = (const float*)d_in[1];
    const float* y      = (const float*)d_in[2];
    const float* W_ih   = (const float*)d_in[3];
    const float* W_hh   = (const float*)d_in[4];
    const float* b_ih   = (const float*)d_in[5];
    const float* b_hh   = (const float*)d_in[6];
    const float* W_eta  = (const float*)d_in[7];
    const float* b_eta  = (const float*)d_in[8];
    const float* W_xi   = (const float*)d_in[9];
    const float* b_xi   = (const float*)d_in[10];
    const float* W_zeta = (const float*)d_in[11];
    const float* b_zeta = (const float*)d_in[12];

    lstm_persist<<<NBLK, THREADS>>>(x, a, y, W_ih, W_hh, b_ih, b_hh,
                                    W_eta, b_eta, W_xi, b_xi, W_zeta, b_zeta,
                                    (float*)d_out);
}

// round 4
// speedup vs baseline: 1.7352x; 1.7352x over previous
#include <cuda_runtime.h>

#define T_STEPS 1024
#define BATCH   256
#define HID     512
#define NBLK    128
#define THREADS 256
#define KHALF   (HID / 2)         // 256 k per split
#define UPB     4                 // hidden units per block
#define GROWS   16                // gate rows per block (4 units x 4 gates)

// Persistent device state (allocation-free scratch)
__device__ float g_h[2][HID * BATCH];   // h[k][b]
__device__ float g_zxT[64 * BATCH];     // zx transposed [col][b]
__device__ float g_zeT[16 * BATCH];     // ze logits transposed [col][b]
__device__ unsigned int g_cnt;          // zero-initialized
__device__ unsigned int g_gen;          // zero-initialized

// ---------- helpers ----------
__device__ __forceinline__ void ffma2(unsigned long long& d,
                                      unsigned long long a,
                                      unsigned long long b) {
    asm("fma.rn.f32x2 %0, %1, %2, %0;" : "+l"(d) : "l"(a), "l"(b));
}
__device__ __forceinline__ unsigned long long addf32x2(unsigned long long a,
                                                       unsigned long long b) {
    unsigned long long r;
    asm("add.rn.f32x2 %0, %1, %2;" : "=l"(r) : "l"(a), "l"(b));
    return r;
}
__device__ __forceinline__ unsigned long long bcast2(float v) {
    unsigned long long r;
    asm("mov.b64 %0, {%1, %1};" : "=l"(r) : "f"(v));
    return r;
}
__device__ __forceinline__ unsigned long long pack2(float lo, float hi) {
    unsigned long long r;
    asm("mov.b64 %0, {%1, %2};" : "=l"(r) : "f"(lo), "f"(hi));
    return r;
}
__device__ __forceinline__ float lo2(unsigned long long v) {
    return __uint_as_float((unsigned int)v);
}
__device__ __forceinline__ float hi2(unsigned long long v) {
    return __uint_as_float((unsigned int)(v >> 32));
}
__device__ __forceinline__ float sigf(float v) {
    return __fdividef(1.0f, 1.0f + __expf(-v));
}
__device__ __forceinline__ float tanh_fast(float v) {
    return __fdividef(2.0f, 1.0f + __expf(-2.0f * v)) - 1.0f;
}

// Generation-counter grid barrier (all NBLK blocks participate)
__device__ __forceinline__ void gsync() {
    __syncthreads();
    if (threadIdx.x == 0) {
        volatile unsigned int* genp = &g_gen;
        unsigned int g = *genp;
        __threadfence();
        if (atomicAdd(&g_cnt, 1u) == NBLK - 1u) {
            atomicExch(&g_cnt, 0u);
            __threadfence();
            *genp = g + 1u;
        } else {
            while (*genp == g) { }
        }
    }
    __syncthreads();
}

// ---------- main persistent kernel ----------
extern "C" __global__ void __launch_bounds__(THREADS, 1)
lstm_persist(const float* __restrict__ x, const float* __restrict__ a,
             const float* __restrict__ y,
             const float* __restrict__ W_ih, const float* __restrict__ W_hh,
             const float* __restrict__ b_ih, const float* __restrict__ b_hh,
             const float* __restrict__ W_eta, const float* __restrict__ b_eta,
             const float* __restrict__ W_xi,  const float* __restrict__ b_xi,
             const float* __restrict__ W_zeta, const float* __restrict__ b_zeta,
             float* __restrict__ out) {
    __shared__ __align__(16) float sW[HID * GROWS];          // [k][16] = 32 KB
    __shared__ float sWx[GROWS], sWa[GROWS], sWy[GROWS], sB[GROWS];
    // Reduction buffer, transposed [p][b2] -> conflict-free STS/LDS.64
    __shared__ unsigned long long sred[16 * 128];            // 16 KB

    const int tid = threadIdx.x;
    const int b2  = tid & 127;       // batch pair index: batches 2*b2, 2*b2+1
    const int kh  = tid >> 7;        // k-half (warp-aligned: warps 0-3 / 4-7)
    const int bid = blockIdx.x;
    const int j0  = bid * UPB;       // first hidden unit owned by this block

    // Load this block's W_hh slice into smem, transposed to [k][local_row].
    // local row l = u*4 + g  ->  global gate row = g*HID + j0 + u
    for (int idx = tid; idx < HID * GROWS; idx += THREADS) {
        int k = idx >> 4, l = idx & 15;
        int u = l >> 2,  g = l & 3;
        int row = g * HID + j0 + u;
        sW[k * GROWS + l] = W_hh[row * HID + k];
    }
    if (tid < GROWS) {
        int u = tid >> 2, g = tid & 3;
        int row = g * HID + j0 + u;
        sWx[tid] = W_ih[row * 3 + 0];
        sWa[tid] = W_ih[row * 3 + 1];
        sWy[tid] = W_ih[row * 3 + 2];
        sB[tid]  = b_ih[row] + b_hh[row];
    }

    // Zero h state; cell state for the 4 owned units x 2 batches in registers.
    float c[2][UPB];
    #pragma unroll
    for (int u = 0; u < UPB; u++) { c[0][u] = 0.0f; c[1][u] = 0.0f; }
    if (kh == 0) {
        #pragma unroll
        for (int u = 0; u < UPB; u++)
            __stcg(reinterpret_cast<float2*>(&g_h[0][(j0 + u) * BATCH + 2 * b2]),
                   make_float2(0.0f, 0.0f));
    }
    gsync();

    const float* sWk = sW + kh * KHALF * GROWS;   // this half's weight base

    int cur = 0;
    for (int s = 0; s < T_STEPS; s++) {
        const int t = T_STEPS - 1 - s;   // reversed sequence

        // acc[0..7]: batch 2*b2 gate pairs; acc[8..15]: batch 2*b2+1.
        unsigned long long acc[16];
        if (kh == 0) {
            const float2 xv = __ldg(reinterpret_cast<const float2*>(&x[t * BATCH + 2 * b2]));
            const float2 av = __ldg(reinterpret_cast<const float2*>(&a[t * BATCH + 2 * b2]));
            const float2 yv = __ldg(reinterpret_cast<const float2*>(&y[t * BATCH + 2 * b2]));
            #pragma unroll
            for (int p = 0; p < 8; p++) {
                float wx0 = sWx[2*p], wx1 = sWx[2*p+1];
                float wa0 = sWa[2*p], wa1 = sWa[2*p+1];
                float wy0 = sWy[2*p], wy1 = sWy[2*p+1];
                float bb0 = sB[2*p],  bb1 = sB[2*p+1];
                acc[p] = pack2(
                    fmaf(wx0, xv.x, fmaf(wa0, av.x, fmaf(wy0, yv.x, bb0))),
                    fmaf(wx1, xv.x, fmaf(wa1, av.x, fmaf(wy1, yv.x, bb1))));
                acc[8 + p] = pack2(
                    fmaf(wx0, xv.y, fmaf(wa0, av.y, fmaf(wy0, yv.y, bb0))),
                    fmaf(wx1, xv.y, fmaf(wa1, av.y, fmaf(wy1, yv.y, bb1))));
            }
        } else {
            #pragma unroll
            for (int p = 0; p < 16; p++) acc[p] = 0ull;
        }

        // h slice: k in [kh*KHALF, kh*KHALF + KHALF). h[k][b]: float2 idx k*128 + b2.
        const float2* hbase =
            reinterpret_cast<const float2*>(g_h[cur]) + kh * KHALF * 128 + b2;

        float2 hbuf[4];
        #pragma unroll
        for (int i = 0; i < 4; i++) hbuf[i] = __ldcg(hbase + i * 128);

        for (int kb = 0; kb < KHALF; kb += 4) {
            #pragma unroll
            for (int j = 0; j < 4; j++) {
                float2 hv = hbuf[j];
                int ni = kb + 4 + j;
                hbuf[j] = (ni < KHALF) ? __ldcg(hbase + ni * 128)
                                       : make_float2(0.0f, 0.0f);

                const ulonglong2* wr =
                    reinterpret_cast<const ulonglong2*>(sWk + (kb + j) * GROWS);
                ulonglong2 w0 = wr[0], w1 = wr[1], w2 = wr[2], w3 = wr[3];
                unsigned long long ha = bcast2(hv.x);
                unsigned long long hb = bcast2(hv.y);
                ffma2(acc[0], ha, w0.x); ffma2(acc[1], ha, w0.y);
                ffma2(acc[2], ha, w1.x); ffma2(acc[3], ha, w1.y);
                ffma2(acc[4], ha, w2.x); ffma2(acc[5], ha, w2.y);
                ffma2(acc[6], ha, w3.x); ffma2(acc[7], ha, w3.y);
                ffma2(acc[8],  hb, w0.x); ffma2(acc[9],  hb, w0.y);
                ffma2(acc[10], hb, w1.x); ffma2(acc[11], hb, w1.y);
                ffma2(acc[12], hb, w2.x); ffma2(acc[13], hb, w2.y);
                ffma2(acc[14], hb, w3.x); ffma2(acc[15], hb, w3.y);
            }
        }

        // Cross-half reduction through smem (transposed layout, conflict-free).
        if (kh == 1) {
            #pragma unroll
            for (int p = 0; p < 16; p++) sred[p * 128 + b2] = acc[p];
        }
        __syncthreads();

        if (kh == 0) {
            #pragma unroll
            for (int p = 0; p < 16; p++)
                acc[p] = addf32x2(acc[p], sred[p * 128 + b2]);

            // Gates + state update for 4 owned units x 2 batches.
            float h0[UPB], h1[UPB];
            #pragma unroll
            for (int u = 0; u < UPB; u++) {
                // pair (2u) = (i, f), pair (2u+1) = (g, o)
                float cn0 = sigf(hi2(acc[2*u])) * c[0][u]
                          + sigf(lo2(acc[2*u])) * tanh_fast(lo2(acc[2*u+1]));
                h0[u] = sigf(hi2(acc[2*u+1])) * tanh_fast(cn0);
                c[0][u] = cn0;
                float cn1 = sigf(hi2(acc[8+2*u])) * c[1][u]
                          + sigf(lo2(acc[8+2*u])) * tanh_fast(lo2(acc[8+2*u+1]));
                h1[u] = sigf(hi2(acc[8+2*u+1])) * tanh_fast(cn1);
                c[1][u] = cn1;
            }
            float* hout = g_h[cur ^ 1];
            #pragma unroll
            for (int u = 0; u < UPB; u++)
                __stcg(reinterpret_cast<float2*>(&hout[(j0 + u) * BATCH + 2 * b2]),
                       make_float2(h0[u], h1[u]));
        }
        gsync();
        cur ^= 1;
    }

    const float* hf = g_h[cur];   // final hidden state [k][b]
    const int b = tid;            // one batch per thread for head phases

    // ---- Phase A: zx columns (blocks 0..63), ze logits (blocks 64..79) ----
    if (bid < 64) {
        const int m = bid;
        float acc = b_xi[m];
        const float* wm = W_xi + m * HID;
        #pragma unroll 8
        for (int k = 0; k < HID; k++)
            acc = fmaf(__ldcg(hf + k * BATCH + b), __ldg(&wm[k]), acc);
        out[b * 64 + m] = acc;                  // zx at offset 0: [B][64]
        __stcg(&g_zxT[m * BATCH + b], acc);
    } else if (bid < 80) {
        const int e = bid - 64;
        float acc = b_eta[e];
        const float* we = W_eta + e * HID;
        #pragma unroll 8
        for (int k = 0; k < HID; k++)
            acc = fmaf(__ldcg(hf + k * BATCH + b), __ldg(&we[k]), acc);
        __stcg(&g_zeT[e * BATCH + b], acc);
    }
    gsync();

    // ---- Phase B: zy columns (blocks 0..63), ze softmax (block 64) ----
    if (bid < 64) {
        const int m = bid;
        float acc = b_zeta[m];
        const float* wz = W_zeta + m * (HID + 64);
        #pragma unroll 8
        for (int k = 0; k < HID; k++)
            acc = fmaf(__ldcg(hf + k * BATCH + b), __ldg(&wz[k]), acc);
        #pragma unroll
        for (int j = 0; j < 64; j++)
            acc = fmaf(__ldcg(&g_zxT[j * BATCH + b]), __ldg(&wz[HID + j]), acc);
        out[16384 + b * 64 + m] = acc;          // zy at offset 16384: [B][64]
    } else if (bid == 64) {
        float l[16];
        float mx = -1e30f;
        #pragma unroll
        for (int e = 0; e < 16; e++) {
            l[e] = __ldcg(&g_zeT[e * BATCH + b]);
            mx = fmaxf(mx, l[e]);
        }
        float ssum = 0.0f;
        #pragma unroll
        for (int e = 0; e < 16; e++) { l[e] = __expf(l[e] - mx); ssum += l[e]; }
        float inv = __fdividef(1.0f, ssum);
        #pragma unroll
        for (int e = 0; e < 16; e++)
            out[32768 + b * 16 + e] = l[e] * inv;   // ze at offset 32768: [B][16]
    }
}

extern "C" void kernel_launch(void* const* d_in, const int* in_sizes, int n_in,
                              void* d_out, int out_size) {
    const float* x      = (const float*)d_in[0];
    const float* a      = (const float*)d_in[1];
    const float* y      = (const float*)d_in[2];
    const float* W_ih   = (const float*)d_in[3];
    const float* W_hh   = (const float*)d_in[4];
    const float* b_ih   = (const float*)d_in[5];
    const float* b_hh   = (const float*)d_in[6];
    const float* W_eta  = (const float*)d_in[7];
    const float* b_eta  = (const float*)d_in[8];
    const float* W_xi   = (const float*)d_in[9];
    const float* b_xi   = (const float*)d_in[10];
    const float* W_zeta = (const float*)d_in[11];
    const float* b_zeta = (const float*)d_in[12];

    lstm_persist<<<NBLK, THREADS>>>(x, a, y, W_ih, W_hh, b_ih, b_hh,
                                    W_eta, b_eta, W_xi, b_xi, W_zeta, b_zeta,
                                    (float*)d_out);
}